// round 5
// baseline (speedup 1.0000x reference)
#include <cuda_runtime.h>
#include <cuda_fp16.h>
#include <math.h>
#include <stdint.h>

// ---------------------------------------------------------------------------
// Problem constants
// ---------------------------------------------------------------------------
#define M_TOK   11520
#define DIM     512
#define HID     1960
#define BPRIME  16
#define NCH     40
#define OH      20
#define OW      36
#define LVEC    720
#define HP      66
#define WP      114
#define NPIX    (BPRIME*NCH*HP*WP)

#define N1PAD   2048
#define K2PAD   1984

// Scratch
__device__ float  g_h  [(size_t)M_TOK * HID];
__device__ float  g_pix[(size_t)NPIX];
__device__ __half g_A1 [(size_t)M_TOK * DIM];
__device__ __half g_B1 [(size_t)N1PAD * DIM];
__device__ __half g_A2 [(size_t)M_TOK * K2PAD];
__device__ __half g_B2 [(size_t)DIM   * K2PAD];

__device__ __forceinline__ float gelu_exact(float v) {
    return 0.5f * v * (1.0f + erff(v * 0.70710678118654752f));
}

// ---------------------------------------------------------------------------
// operand prep kernels
// ---------------------------------------------------------------------------
__global__ void prep_x_kernel(const float* __restrict__ x, __half* __restrict__ A1)
{
    int idx = blockIdx.x * blockDim.x + threadIdx.x;
    if (idx >= M_TOK * DIM) return;
    A1[idx] = __float2half(x[idx]);
}

__global__ void prep_W1_kernel(const float* __restrict__ W1, __half* __restrict__ B1)
{
    int idx = blockIdx.x * blockDim.x + threadIdx.x;
    if (idx >= N1PAD * DIM) return;
    int n = idx / DIM, k = idx - n * DIM;
    float v = (n < HID) ? W1[(size_t)n * DIM + k] : 0.0f;
    B1[idx] = __float2half(v);
}

__global__ void prep_W2_kernel(const float* __restrict__ W2, __half* __restrict__ B2)
{
    int idx = blockIdx.x * blockDim.x + threadIdx.x;
    if (idx >= DIM * K2PAD) return;
    int n = idx / K2PAD, j = idx - n * K2PAD;
    float v = (j < HID) ? W2[(size_t)n * HID + j] : 0.0f;
    B2[idx] = __float2half(v);
}

__global__ void prep_A2_kernel(const float* __restrict__ pix, __half* __restrict__ A2)
{
    long long idx = (long long)blockIdx.x * blockDim.x + threadIdx.x;
    if (idx >= (long long)M_TOK * K2PAD) return;
    int token = (int)(idx / K2PAD);
    int j     = (int)(idx - (long long)token * K2PAD);
    float g = 0.0f;
    if (j < HID) {
        int b  = token / LVEC;
        int l  = token - b * LVEC;
        int oy = l / OW, ox = l - oy * OW;
        int c  = j / 49;
        int r  = j - c * 49;
        int kh = r / 7, kw = r - kh * 7;
        int iy = kh + 3 * oy;
        int ix = kw + 3 * ox;
        float y = pix[(((size_t)b * NCH + c) * HP + iy) * WP + ix];
        g = gelu_exact(y);
    }
    A2[idx] = __float2half(g);
}

// ---------------------------------------------------------------------------
// fold + normalize + border-mask
// ---------------------------------------------------------------------------
__global__ void fold_div_kernel(const float* __restrict__ h, float* __restrict__ pix)
{
    int idx = blockIdx.x * blockDim.x + threadIdx.x;
    if (idx >= NPIX) return;
    int ix = idx % WP;
    int t  = idx / WP;
    int iy = t % HP;  t /= HP;
    int c  = t % NCH;
    int b  = t / NCH;

    float val = 0.0f;
    if (iy >= 3 && iy < 63 && ix >= 3 && ix < 111) {
        int oy_lo = max(0, (iy - 4) / 3);
        int oy_hi = min(OH - 1, iy / 3);
        int ox_lo = max(0, (ix - 4) / 3);
        int ox_hi = min(OW - 1, ix / 3);
        int cnt = (oy_hi - oy_lo + 1) * (ox_hi - ox_lo + 1);
        float acc = 0.0f;
        for (int oy = oy_lo; oy <= oy_hi; oy++) {
            int kh = iy - 3 * oy;
            for (int ox = ox_lo; ox <= ox_hi; ox++) {
                int kw = ix - 3 * ox;
                int token = b * LVEC + oy * OW + ox;
                acc += h[(size_t)token * HID + c * 49 + kh * 7 + kw];
            }
        }
        val = acc / (float)cnt;
    }
    pix[idx] = val;
}

// ---------------------------------------------------------------------------
// fp16 mma.sync GEMM, templated tiles.
// C[m,n] = sum_k A[m,k]*B[n,k] + bias[n]
// BM=128 fixed. 8 warps: (128/32) x (BN/WN)=2. Warp tile 32 x WN.
// BK=64 halves (128B SW128 rows), 3-stage cp.async, register double-buffer.
// ---------------------------------------------------------------------------
#define STAGES 3

__device__ __forceinline__ uint32_t smem_u32(const void* p) {
    return (uint32_t)__cvta_generic_to_shared(p);
}

template<int BN, int WN, int MINCTA>
__global__ __launch_bounds__(256, MINCTA)
void gemm_fp16_mma(const __half* __restrict__ A, const __half* __restrict__ B,
                   const float* __restrict__ bias, float* __restrict__ C,
                   int KT, int kbytes, int Nstore, int ldc)
{
    constexpr int STAGE_BYTES = (128 + BN) * 128;
    constexpr int NB16 = WN / 16;   // b x4-ldmatrix per k16
    constexpr int NJ   = WN / 8;    // mma n-steps

    extern __shared__ char smem[];
    uint32_t sbase = smem_u32(smem);
    const int tid  = threadIdx.x;
    const int wid  = tid >> 5;
    const int lane = tid & 31;
    const int wm   = wid >> 1;
    const int wn   = wid & 1;
    const int m0   = blockIdx.y * 128;
    const int n0   = blockIdx.x * BN;

    const char* Ab = (const char*)A + (size_t)m0 * kbytes;
    const char* Bb = (const char*)B + (size_t)n0 * kbytes;

    float acc[2][NJ][4];
#pragma unroll
    for (int i = 0; i < 2; i++)
#pragma unroll
        for (int j = 0; j < NJ; j++)
#pragma unroll
            for (int q = 0; q < 4; q++) acc[i][j][q] = 0.0f;

    auto load_stage = [&](int s, int kt2) {
        uint32_t st = sbase + s * STAGE_BYTES;
        size_t koff = (size_t)kt2 * 128;
#pragma unroll
        for (int i = 0; i < 4; i++) {               // A: 128 rows * 8 chunks
            int id  = tid + i * 256;
            int row = id >> 3;
            int c   = id & 7;
            uint32_t so = (uint32_t)(row * 128 + ((c ^ (row & 7)) << 4));
            const char* ga = Ab + (size_t)row * kbytes + koff + ((size_t)c << 4);
            asm volatile("cp.async.cg.shared.global [%0], [%1], 16;" :: "r"(st + so), "l"(ga) : "memory");
        }
#pragma unroll
        for (int i = 0; i < BN / 32; i++) {         // B: BN rows * 8 chunks
            int id  = tid + i * 256;
            int row = id >> 3;
            int c   = id & 7;
            uint32_t so = (uint32_t)(row * 128 + ((c ^ (row & 7)) << 4));
            const char* gb = Bb + (size_t)row * kbytes + koff + ((size_t)c << 4);
            asm volatile("cp.async.cg.shared.global [%0], [%1], 16;" :: "r"(st + 16384 + so), "l"(gb) : "memory");
        }
        asm volatile("cp.async.commit_group;" ::: "memory");
    };

    const int lrow = lane & 15;
    const int lch  = lane >> 4;

    auto load_frags = [&](int k16, uint32_t (&a)[2][4], uint32_t (&b)[NB16][4],
                          uint32_t sA, uint32_t sB) {
#pragma unroll
        for (int i = 0; i < 2; i++) {
            int r = wm * 32 + i * 16 + lrow;
            uint32_t addr = sA + r * 128 + (((2 * k16 + lch) ^ (r & 7)) << 4);
            asm volatile("ldmatrix.sync.aligned.m8n8.x4.shared.b16 {%0,%1,%2,%3}, [%4];"
                         : "=r"(a[i][0]), "=r"(a[i][1]), "=r"(a[i][2]), "=r"(a[i][3])
                         : "r"(addr));
        }
#pragma unroll
        for (int j = 0; j < NB16; j++) {
            int r = wn * WN + j * 16 + lrow;
            uint32_t addr = sB + r * 128 + (((2 * k16 + lch) ^ (r & 7)) << 4);
            asm volatile("ldmatrix.sync.aligned.m8n8.x4.shared.b16 {%0,%1,%2,%3}, [%4];"
                         : "=r"(b[j][0]), "=r"(b[j][1]), "=r"(b[j][2]), "=r"(b[j][3])
                         : "r"(addr));
        }
    };

    auto mma_block = [&](uint32_t (&a)[2][4], uint32_t (&b)[NB16][4]) {
#pragma unroll
        for (int i = 0; i < 2; i++) {
#pragma unroll
            for (int jn = 0; jn < NJ; jn++) {
                int jj = jn >> 1;
                uint32_t b0 = (jn & 1) ? b[jj][1] : b[jj][0];
                uint32_t b1 = (jn & 1) ? b[jj][3] : b[jj][2];
                asm volatile(
                    "mma.sync.aligned.m16n8k16.row.col.f32.f16.f16.f32 "
                    "{%0,%1,%2,%3}, {%4,%5,%6,%7}, {%8,%9}, {%0,%1,%2,%3};"
                    : "+f"(acc[i][jn][0]), "+f"(acc[i][jn][1]),
                      "+f"(acc[i][jn][2]), "+f"(acc[i][jn][3])
                    : "r"(a[i][0]), "r"(a[i][1]), "r"(a[i][2]), "r"(a[i][3]),
                      "r"(b0), "r"(b1));
            }
        }
    };

    // prologue
#pragma unroll
    for (int p = 0; p < STAGES - 1; p++) load_stage(p, p);

    for (int kt = 0; kt < KT; kt++) {
        int s = kt % STAGES;
        asm volatile("cp.async.wait_group 1;" ::: "memory");
        __syncthreads();

        int ktn = kt + STAGES - 1;
        if (ktn < KT) load_stage(ktn % STAGES, ktn);
        else          asm volatile("cp.async.commit_group;" ::: "memory");

        uint32_t sA = sbase + s * STAGE_BYTES;
        uint32_t sB = sA + 16384;

        uint32_t afr[2][2][4], bfr[2][NB16][4];
        load_frags(0, afr[0], bfr[0], sA, sB);
#pragma unroll
        for (int k16 = 0; k16 < 4; k16++) {
            int cur = k16 & 1;
            if (k16 < 3) load_frags(k16 + 1, afr[cur ^ 1], bfr[cur ^ 1], sA, sB);
            mma_block(afr[cur], bfr[cur]);
        }
    }

    // epilogue
    const int g  = lane >> 2;
    const int tg = lane & 3;
#pragma unroll
    for (int i = 0; i < 2; i++) {
        int r0 = m0 + wm * 32 + i * 16 + g;
#pragma unroll
        for (int jn = 0; jn < NJ; jn++) {
            int col = n0 + wn * WN + jn * 8 + tg * 2;
            if (col < Nstore) {
                float bx = bias[col], by = bias[col + 1];
                float2 v0 = make_float2(acc[i][jn][0] + bx, acc[i][jn][1] + by);
                float2 v1 = make_float2(acc[i][jn][2] + bx, acc[i][jn][3] + by);
                *reinterpret_cast<float2*>(C + (size_t)r0       * ldc + col) = v0;
                *reinterpret_cast<float2*>(C + (size_t)(r0 + 8) * ldc + col) = v1;
            }
        }
    }
}

// ---------------------------------------------------------------------------
// launch
// ---------------------------------------------------------------------------
extern "C" void kernel_launch(void* const* d_in, const int* in_sizes, int n_in,
                              void* d_out, int out_size)
{
    const float* x  = (const float*)d_in[0];
    const float* W1 = (const float*)d_in[1];
    const float* b1 = (const float*)d_in[2];
    const float* W2 = (const float*)d_in[3];
    const float* b2 = (const float*)d_in[4];
    float* out = (float*)d_out;

    float *h_ptr, *pix_ptr;
    __half *A1, *B1, *A2, *B2;
    cudaGetSymbolAddress((void**)&h_ptr,   g_h);
    cudaGetSymbolAddress((void**)&pix_ptr, g_pix);
    cudaGetSymbolAddress((void**)&A1, g_A1);
    cudaGetSymbolAddress((void**)&B1, g_B1);
    cudaGetSymbolAddress((void**)&A2, g_A2);
    cudaGetSymbolAddress((void**)&B2, g_B2);

    constexpr int SMEM1 = STAGES * (128 + 128) * 128;   // 98304
    constexpr int SMEM2 = STAGES * (128 + 64) * 128;    // 73728
    cudaFuncSetAttribute((const void*)gemm_fp16_mma<128, 64, 2>,
                         cudaFuncAttributeMaxDynamicSharedMemorySize, SMEM1);
    cudaFuncSetAttribute((const void*)gemm_fp16_mma<64, 32, 3>,
                         cudaFuncAttributeMaxDynamicSharedMemorySize, SMEM2);

    { int n = M_TOK * DIM;   prep_x_kernel <<<(n + 255) / 256, 256>>>(x,  A1); }
    { int n = N1PAD * DIM;   prep_W1_kernel<<<(n + 255) / 256, 256>>>(W1, B1); }
    { int n = DIM * K2PAD;   prep_W2_kernel<<<(n + 255) / 256, 256>>>(W2, B2); }

    // GEMM1: g_h = x @ W1^T + b1   (M=11520, N=1960(pad2048), K=512)
    {
        dim3 grid(N1PAD / 128, M_TOK / 128);
        gemm_fp16_mma<128, 64, 2><<<grid, 256, SMEM1>>>(A1, B1, b1, h_ptr,
                                                        DIM / 64, DIM * 2, HID, HID);
    }
    // fold + normalize + mask
    {
        int blocks = (NPIX + 255) / 256;
        fold_div_kernel<<<blocks, 256>>>(h_ptr, pix_ptr);
    }
    // unfold + GELU -> A2
    {
        long long n = (long long)M_TOK * K2PAD;
        prep_A2_kernel<<<(int)((n + 255) / 256), 256>>>(pix_ptr, A2);
    }
    // GEMM2: out = gelu(y) @ W2^T + b2   (M=11520, N=512, K=1960(pad1984))
    {
        dim3 grid(DIM / 64, M_TOK / 128);
        gemm_fp16_mma<64, 32, 3><<<grid, 256, SMEM2>>>(A2, B2, b2, out,
                                                       K2PAD / 64, K2PAD * 2, DIM, DIM);
    }
}